// round 10
// baseline (speedup 1.0000x reference)
#include <cuda_runtime.h>
#include <cuda_bf16.h>
#include <math.h>

#define NPTS 32768
#define CIN  32
#define F0   256
#define KATT 1024
#define BSEG 16
#define KC   32768
#define EPAD 40
#define BN_EPS 1e-5f

#define TILE_N 128
#define SETU 68            /* uint stride of sEt row (128 pts bf16 + pad) */
#define SETB 136
#define SXTU 68
#define STAGE_U (128 * 36 * 2)
#define SMEM_A_U (2 * STAGE_U)          /* k2a mainloop: 73728 B */
#define SMEM_B_U (128 * SETU + 40 * SXTU)  /* k2b: 8704+2720=11424 u = 45696 B */

// ---------------- scratch ----------------
__device__ unsigned g_att1b[NPTS * 128];   // bf16x2-packed att1
__device__ unsigned g_w2b[KATT * 128];     // bf16x2-packed w2
__device__ unsigned g_eb[(long)KATT * (NPTS / 2)]; // e transposed [col][pt-pair], 67 MB
__device__ float g_E[BSEG * KATT * EPAD];
__device__ float g_out2[BSEG * KC];
__device__ float g_rtmp[BSEG * F0];
__device__ float g_s1[F0], g_t1[F0];
__device__ float g_s2[KATT], g_t2[KATT];
__device__ float g_s3[F0], g_t3[F0];
__device__ int   g_off[BSEG + 1];

// ---------------- helpers ----------------
static __device__ __forceinline__ unsigned utf32(float x) {
    unsigned r;
    asm("cvt.rna.tf32.f32 %0, %1;" : "=r"(r) : "f"(x));
    return r;
}

static __device__ __forceinline__ unsigned packbf(float lo, float hi) {
    unsigned r;
    asm("cvt.rn.bf16x2.f32 %0, %1, %2;" : "=r"(r) : "f"(hi), "f"(lo));
    return r;
}

static __device__ __forceinline__ void mma_tf32(float* d, const unsigned* a, const unsigned* b) {
    asm volatile(
        "mma.sync.aligned.m16n8k8.row.col.f32.tf32.tf32.f32 "
        "{%0,%1,%2,%3}, {%4,%5,%6,%7}, {%8,%9}, {%0,%1,%2,%3};\n"
        : "+f"(d[0]), "+f"(d[1]), "+f"(d[2]), "+f"(d[3])
        : "r"(a[0]), "r"(a[1]), "r"(a[2]), "r"(a[3]), "r"(b[0]), "r"(b[1]));
}

static __device__ __forceinline__ void mma_bf16(float* d, const unsigned* a, const unsigned* b) {
    asm volatile(
        "mma.sync.aligned.m16n8k16.row.col.f32.bf16.bf16.f32 "
        "{%0,%1,%2,%3}, {%4,%5,%6,%7}, {%8,%9}, {%0,%1,%2,%3};\n"
        : "+f"(d[0]), "+f"(d[1]), "+f"(d[2]), "+f"(d[3])
        : "r"(a[0]), "r"(a[1]), "r"(a[2]), "r"(a[3]), "r"(b[0]), "r"(b[1]));
}

static __device__ __forceinline__ void ldsm4(unsigned& r0, unsigned& r1, unsigned& r2,
                                             unsigned& r3, unsigned a) {
    asm volatile("ldmatrix.sync.aligned.m8n8.x4.shared.b16 {%0,%1,%2,%3}, [%4];"
                 : "=r"(r0), "=r"(r1), "=r"(r2), "=r"(r3) : "r"(a));
}

static __device__ __forceinline__ void cpa16(void* s, const void* g) {
    unsigned sa = (unsigned)__cvta_generic_to_shared(s);
    asm volatile("cp.async.cg.shared.global [%0], [%1], 16;\n" :: "r"(sa), "l"(g));
}
#define CPA_COMMIT() asm volatile("cp.async.commit_group;\n" ::: "memory")
#define CPA_WAIT0()  asm volatile("cp.async.wait_group 0;\n" ::: "memory")

static __device__ __forceinline__ int seg_of(int row) {
    int s = 0;
    while (s < BSEG - 1 && row >= g_off[s + 1]) s++;
    return s;
}

// ---------------- k0_prep ----------------
__global__ void k0_prep(const int* __restrict__ len,
                        const float* __restrict__ b1, const float* __restrict__ g1,
                        const float* __restrict__ be1, const float* __restrict__ m1,
                        const float* __restrict__ v1,
                        const float* __restrict__ b2, const float* __restrict__ g2,
                        const float* __restrict__ be2, const float* __restrict__ m2,
                        const float* __restrict__ v2,
                        const float* __restrict__ fcb, const float* __restrict__ g3,
                        const float* __restrict__ be3, const float* __restrict__ m3,
                        const float* __restrict__ v3) {
    int t = threadIdx.x;
    if (t == 0) {
        int acc = 0;
        for (int i = 0; i < BSEG; i++) { g_off[i] = acc; acc += len[i]; }
        g_off[BSEG] = acc;
    }
    if (t < F0) {
        float a = g1[t] * rsqrtf(v1[t] + BN_EPS);
        g_s1[t] = a;
        g_t1[t] = (b1[t] - m1[t]) * a + be1[t];
        float a3 = g3[t] * rsqrtf(v3[t] + BN_EPS);
        g_s3[t] = a3;
        g_t3[t] = (fcb[t] - m3[t]) * a3 + be3[t];
    }
    {
        float a2 = g2[t] * rsqrtf(v2[t] + BN_EPS);
        g_s2[t] = a2;
        g_t2[t] = (b2[t] - m2[t]) * a2 + be2[t];
    }
}

// ---------------- k0_zero ----------------
__global__ void k0_zero(const float* __restrict__ w2) {
    int idx = blockIdx.x * 256 + threadIdx.x;
    if (idx < BSEG * KATT * EPAD) g_E[idx] = 0.f;
    if (idx < BSEG * F0) g_rtmp[idx] = 0.f;
    if (idx < KATT * 128) {
        int n = idx >> 7, p = idx & 127;
        g_w2b[idx] = packbf(w2[n * F0 + 2 * p], w2[n * F0 + 2 * p + 1]);
    }
}

// ---------------- k1: att1 = relu(bn1(x @ w1^T)) -> bf16 ----------------
__global__ __launch_bounds__(256) void k1_gemm1(const float* __restrict__ x,
                                                const float* __restrict__ w1) {
    __shared__ unsigned sA[128 * 36];
    __shared__ unsigned sB[128 * 36];
    int tid = threadIdx.x;
    int rowBase = blockIdx.x * 128;
    int colBase = blockIdx.y * 128;

#pragma unroll
    for (int i = 0; i < 16; i++) {
        int idx = tid + i * 256;
        int r = idx >> 5, c = idx & 31;
        sA[r * 36 + c] = utf32(x[(rowBase + r) * CIN + c]);
        sB[r * 36 + c] = utf32(w1[(colBase + r) * CIN + c]);
    }
    __syncthreads();

    int wid = tid >> 5, lane = tid & 31;
    int g = lane >> 2, tg = lane & 3;
    int wr = (wid & 1) * 64;
    int wc = (wid >> 1) * 32;
    float acc[4][4][4] = {};

#pragma unroll
    for (int ks = 0; ks < 32; ks += 8) {
        unsigned af[4][4], bf[4][2];
#pragma unroll
        for (int mt = 0; mt < 4; mt++) {
            int r0 = wr + mt * 16 + g;
            af[mt][0] = sA[r0 * 36 + ks + tg];
            af[mt][1] = sA[(r0 + 8) * 36 + ks + tg];
            af[mt][2] = sA[r0 * 36 + ks + tg + 4];
            af[mt][3] = sA[(r0 + 8) * 36 + ks + tg + 4];
        }
#pragma unroll
        for (int nt = 0; nt < 4; nt++) {
            int n0 = wc + nt * 8 + g;
            bf[nt][0] = sB[n0 * 36 + ks + tg];
            bf[nt][1] = sB[n0 * 36 + ks + tg + 4];
        }
#pragma unroll
        for (int mt = 0; mt < 4; mt++)
#pragma unroll
            for (int nt = 0; nt < 4; nt++) mma_tf32(acc[mt][nt], af[mt], bf[nt]);
    }

#pragma unroll
    for (int mt = 0; mt < 4; mt++) {
#pragma unroll
        for (int nt = 0; nt < 4; nt++) {
            int col = colBase + wc + nt * 8 + 2 * tg;
            float s0 = g_s1[col], t0 = g_t1[col];
            float s1v = g_s1[col + 1], t1v = g_t1[col + 1];
            int r0 = rowBase + wr + mt * 16 + g;
            float v0 = fmaxf(acc[mt][nt][0] * s0 + t0, 0.f);
            float v1 = fmaxf(acc[mt][nt][1] * s1v + t1v, 0.f);
            float v2 = fmaxf(acc[mt][nt][2] * s0 + t0, 0.f);
            float v3 = fmaxf(acc[mt][nt][3] * s1v + t1v, 0.f);
            g_att1b[r0 * 128 + (col >> 1)] = packbf(v0, v1);
            g_att1b[(r0 + 8) * 128 + (col >> 1)] = packbf(v2, v3);
        }
    }
}

// ---------------- k2a: bf16 GEMM2 + bn2 + relu + exp -> g_eb (pure, no pooling) ----------------
__global__ __launch_bounds__(256, 2) void k2a_gemm(int dummy) {
    extern __shared__ unsigned sm[];
    unsigned* sEtU = sm;                 // [128 attcols][68], aliased over stage bufs

    int tid = threadIdx.x;
    int rowBase = blockIdx.x * 128;
    int colBase = blockIdx.y * TILE_N;
    int wid = tid >> 5, lane = tid & 31;
    int g = lane >> 2, tg = lane & 3;
    int wr = (wid & 1) * 64;
    int wc = (wid >> 1) * 32;
    float acc[4][4][4] = {};

    const unsigned* gA = g_att1b + (long)rowBase * 128;
    const unsigned* gB = g_w2b + (long)colBase * 128;
    unsigned smBase = (unsigned)__cvta_generic_to_shared(sm);

    int aRowL = (lane & 7) + ((lane >> 3) & 1) * 8;
    int aKoff = (lane >> 4) << 2;
    int bRowL = (lane & 7) + ((lane >> 4) << 3);
    int bKoff = ((lane >> 3) & 1) << 2;

    {
        unsigned* sA = sm;
        unsigned* sB = sm + 128 * 36;
#pragma unroll
        for (int i = 0; i < 4; i++) {
            int u = tid + i * 256;
            int r = u >> 3, cu = u & 7;
            cpa16(sA + r * 36 + cu * 4, gA + (long)r * 128 + cu * 4);
        }
#pragma unroll
        for (int i = 0; i < 4; i++) {
            int u = tid + i * 256;
            int r = u >> 3, cu = u & 7;
            cpa16(sB + r * 36 + cu * 4, gB + (long)r * 128 + cu * 4);
        }
        CPA_COMMIT();
    }

    for (int c = 0; c < 4; c++) {
        CPA_WAIT0();
        __syncthreads();

        if (c + 1 < 4) {
            unsigned* sA = sm + ((c + 1) & 1) * STAGE_U;
            unsigned* sB = sA + 128 * 36;
            int ku = (c + 1) * 32;
#pragma unroll
            for (int i = 0; i < 4; i++) {
                int u = tid + i * 256;
                int r = u >> 3, cu = u & 7;
                cpa16(sA + r * 36 + cu * 4, gA + (long)r * 128 + ku + cu * 4);
            }
#pragma unroll
            for (int i = 0; i < 4; i++) {
                int u = tid + i * 256;
                int r = u >> 3, cu = u & 7;
                cpa16(sB + r * 36 + cu * 4, gB + (long)r * 128 + ku + cu * 4);
            }
            CPA_COMMIT();
        }

        unsigned sAb = smBase + ((c & 1) * STAGE_U) * 4;
        unsigned sBb = sAb + 128 * 36 * 4;

        unsigned aAddr[4], bAddr[2];
#pragma unroll
        for (int mt = 0; mt < 4; mt++)
            aAddr[mt] = sAb + ((wr + mt * 16 + aRowL) * 36 + aKoff) * 4;
#pragma unroll
        for (int p = 0; p < 2; p++)
            bAddr[p] = sBb + ((wc + p * 16 + bRowL) * 36 + bKoff) * 4;

#pragma unroll
        for (int j = 0; j < 4; j++) {
            unsigned af[4][4], bf[4][2];
#pragma unroll
            for (int mt = 0; mt < 4; mt++)
                ldsm4(af[mt][0], af[mt][1], af[mt][2], af[mt][3], aAddr[mt] + j * 32);
#pragma unroll
            for (int p = 0; p < 2; p++)
                ldsm4(bf[2 * p][0], bf[2 * p][1], bf[2 * p + 1][0], bf[2 * p + 1][1],
                      bAddr[p] + j * 32);
#pragma unroll
            for (int mt = 0; mt < 4; mt++)
#pragma unroll
                for (int nt = 0; nt < 4; nt++) mma_bf16(acc[mt][nt], af[mt], bf[nt]);
        }
    }

    __syncthreads();   // all mma smem reads done before aliasing

    // e = exp(relu(bn2(acc))) -> sEt (transposed, bf16)
    __nv_bfloat16* sEtB = (__nv_bfloat16*)sEtU;
#pragma unroll
    for (int mt = 0; mt < 4; mt++) {
#pragma unroll
        for (int nt = 0; nt < 4; nt++) {
            int col = wc + nt * 8 + 2 * tg;
            int colG = colBase + col;
            float s0 = g_s2[colG], t0 = g_t2[colG];
            float s1v = g_s2[colG + 1], t1v = g_t2[colG + 1];
            int r0 = wr + mt * 16 + g;
            float e0 = __expf(fmaxf(acc[mt][nt][0] * s0 + t0, 0.f));
            float e1 = __expf(fmaxf(acc[mt][nt][1] * s1v + t1v, 0.f));
            float e2 = __expf(fmaxf(acc[mt][nt][2] * s0 + t0, 0.f));
            float e3 = __expf(fmaxf(acc[mt][nt][3] * s1v + t1v, 0.f));
            sEtB[col * SETB + r0] = __float2bfloat16_rn(e0);
            sEtB[(col + 1) * SETB + r0] = __float2bfloat16_rn(e1);
            sEtB[col * SETB + r0 + 8] = __float2bfloat16_rn(e2);
            sEtB[(col + 1) * SETB + r0 + 8] = __float2bfloat16_rn(e3);
        }
    }
    __syncthreads();

    // coalesced store: g_eb[colG][ptPair]
#pragma unroll
    for (int i = 0; i < 8; i++) {
        int idx = tid + i * 256;          // 2048 uint4 units
        int col = idx >> 4, q = idx & 15;
        uint4 v = *(uint4*)&sEtU[col * SETU + q * 4];
        *(uint4*)&g_eb[(long)(colBase + col) * (NPTS / 2) + (rowBase >> 1) + q * 4] = v;
    }
}

// ---------------- k2b: pooling  E[s][col][n] += e^T @ x_aug ----------------
__global__ __launch_bounds__(256) void k2b_pool(const float* __restrict__ x) {
    extern __shared__ unsigned sm[];
    unsigned* sEtU = sm;                 // [128 cols][68]
    unsigned* sXtU = sm + 128 * SETU;    // [40][68]

    int tid = threadIdx.x;
    int colBase = blockIdx.x * 128;
    int ptBase = blockIdx.y * 128;
    int wid = tid >> 5, lane = tid & 31;
    int g = lane >> 2, tg = lane & 3;

    // load e tile (cp.async): 128 cols x 64 uints
#pragma unroll
    for (int i = 0; i < 8; i++) {
        int idx = tid + i * 256;          // 2048 16B units
        int col = idx >> 4, q = idx & 15;
        cpa16(sEtU + col * SETU + q * 4,
              g_eb + (long)(colBase + col) * (NPTS / 2) + (ptBase >> 1) + q * 4);
    }
    CPA_COMMIT();

    // x_aug transposed
#pragma unroll
    for (int i = 0; i < 10; i++) {
        int idx = tid + i * 256;
        int n = idx >> 6, pp = idx & 63;
        float lo, hi;
        if (n < 32) {
            lo = x[(long)(ptBase + 2 * pp) * CIN + n];
            hi = x[(long)(ptBase + 2 * pp + 1) * CIN + n];
        } else if (n == 32) { lo = hi = 1.f; }
        else { lo = hi = 0.f; }
        sXtU[n * SXTU + pp] = packbf(lo, hi);
    }
    CPA_WAIT0();
    __syncthreads();

    // per-segment e^T @ x_aug; warp handles 16 cols
    int s0 = seg_of(ptBase), s1 = seg_of(ptBase + 127);
    int mcol = wid * 16;
    for (int s = s0; s <= s1; s++) {
        int lo = max(g_off[s] - ptBase, 0);
        int hi = min(g_off[s + 1] - ptBase, 128);
        float ea[5][4] = {};
        for (int kk = (lo & ~15); kk < hi; kk += 16) {
            int pA = kk + 2 * tg;
            int pB = pA + 8;
            unsigned maskA = ((pA >= lo && pA < hi) ? 0x0000FFFFu : 0u) |
                             ((pA + 1 >= lo && pA + 1 < hi) ? 0xFFFF0000u : 0u);
            unsigned maskB = ((pB >= lo && pB < hi) ? 0x0000FFFFu : 0u) |
                             ((pB + 1 >= lo && pB + 1 < hi) ? 0xFFFF0000u : 0u);
            int ub = (kk >> 1) + tg;
            unsigned af[4];
            af[0] = sEtU[(mcol + g) * SETU + ub] & maskA;
            af[1] = sEtU[(mcol + g + 8) * SETU + ub] & maskA;
            af[2] = sEtU[(mcol + g) * SETU + ub + 4] & maskB;
            af[3] = sEtU[(mcol + g + 8) * SETU + ub + 4] & maskB;
#pragma unroll
            for (int nt = 0; nt < 5; nt++) {
                unsigned bf[2];
                bf[0] = sXtU[(nt * 8 + g) * SXTU + ub];
                bf[1] = sXtU[(nt * 8 + g) * SXTU + ub + 4];
                mma_bf16(ea[nt], af, bf);
            }
        }
#pragma unroll
        for (int nt = 0; nt < 5; nt++) {
            int n = nt * 8 + 2 * tg;
            int ac0 = colBase + mcol + g;
            int ac1 = ac0 + 8;
            if (n <= 32) atomicAdd(&g_E[((long)s * KATT + ac0) * EPAD + n], ea[nt][0]);
            if (n + 1 <= 32) atomicAdd(&g_E[((long)s * KATT + ac0) * EPAD + n + 1], ea[nt][1]);
            if (n <= 32) atomicAdd(&g_E[((long)s * KATT + ac1) * EPAD + n], ea[nt][2]);
            if (n + 1 <= 32) atomicAdd(&g_E[((long)s * KATT + ac1) * EPAD + n + 1], ea[nt][3]);
        }
    }
}

// ---------------- k_out2: warp per (b,k) ----------------
__global__ void k_out2(const int* __restrict__ len) {
    int bk = blockIdx.x * 8 + (threadIdx.x >> 5);
    int lane = threadIdx.x & 31;
    int b = bk >> 10, k = bk & 1023;
    const float* Eb = &g_E[(long)bk * EPAD];
    float rcp = 1.f / (Eb[32] * (float)len[b]);
    g_out2[((long)b << 15) + (k << 5) + lane] = Eb[lane] * rcp;
}

// ---------------- k3 ----------------
__global__ __launch_bounds__(256) void k3_fc(const float* __restrict__ fcw) {
    int wg = blockIdx.x * 8 + (threadIdx.x >> 5);
    int lane = threadIdx.x & 31;
    int jg = wg & 31;
    int slice = wg >> 5;
    int j0 = jg * 8;
    int base = slice * 1024;
    float acc[8][16] = {};
    for (int it = 0; it < 32; it++) {
        int kc = base + it * 32 + lane;
        float w[8];
#pragma unroll
        for (int jj = 0; jj < 8; jj++) w[jj] = fcw[(long)(j0 + jj) * KC + kc];
#pragma unroll
        for (int bb = 0; bb < 16; bb++) {
            float o = g_out2[bb * KC + kc];
#pragma unroll
            for (int jj = 0; jj < 8; jj++) acc[jj][bb] = fmaf(o, w[jj], acc[jj][bb]);
        }
    }
#pragma unroll
    for (int jj = 0; jj < 8; jj++) {
#pragma unroll
        for (int bb = 0; bb < 16; bb++) {
            float v = acc[jj][bb];
            v += __shfl_down_sync(0xffffffffu, v, 16);
            v += __shfl_down_sync(0xffffffffu, v, 8);
            v += __shfl_down_sync(0xffffffffu, v, 4);
            v += __shfl_down_sync(0xffffffffu, v, 2);
            v += __shfl_down_sync(0xffffffffu, v, 1);
            if (lane == 0) atomicAdd(&g_rtmp[bb * F0 + j0 + jj], v);
        }
    }
}

// ---------------- k4 ----------------
__global__ void k4_norm(float* __restrict__ out) {
    int b = blockIdx.x;
    int j = threadIdx.x;
    float v = g_rtmp[b * F0 + j] * g_s3[j] + g_t3[j];
    __shared__ float red[256];
    red[j] = v * v;
    __syncthreads();
    for (int o = 128; o > 0; o >>= 1) {
        if (j < o) red[j] += red[j + o];
        __syncthreads();
    }
    float nrm = fmaxf(sqrtf(red[0]), 1e-12f);
    out[b * F0 + j] = v / nrm;
}

// ---------------- launch ----------------
extern "C" void kernel_launch(void* const* d_in, const int* in_sizes, int n_in,
                              void* d_out, int out_size) {
    const float* x   = (const float*)d_in[0];
    const int*   len = (const int*)d_in[1];
    const float* w1  = (const float*)d_in[2];
    const float* b1  = (const float*)d_in[3];
    const float* g1  = (const float*)d_in[4];
    const float* be1 = (const float*)d_in[5];
    const float* m1  = (const float*)d_in[6];
    const float* v1  = (const float*)d_in[7];
    const float* w2  = (const float*)d_in[8];
    const float* b2  = (const float*)d_in[9];
    const float* g2  = (const float*)d_in[10];
    const float* be2 = (const float*)d_in[11];
    const float* m2  = (const float*)d_in[12];
    const float* v2  = (const float*)d_in[13];
    const float* fcw = (const float*)d_in[14];
    const float* fcb = (const float*)d_in[15];
    const float* g3  = (const float*)d_in[16];
    const float* be3 = (const float*)d_in[17];
    const float* m3  = (const float*)d_in[18];
    const float* v3  = (const float*)d_in[19];
    float* out = (float*)d_out;

    const int k2a_smem = SMEM_A_U * 4;   // 73728 B -> 2 CTAs/SM
    const int k2b_smem = SMEM_B_U * 4;   // 45696 B
    cudaFuncSetAttribute(k2a_gemm, cudaFuncAttributeMaxDynamicSharedMemorySize, k2a_smem);
    cudaFuncSetAttribute(k2b_pool, cudaFuncAttributeMaxDynamicSharedMemorySize, k2b_smem);

    k0_prep<<<1, 1024>>>(len, b1, g1, be1, m1, v1, b2, g2, be2, m2, v2,
                         fcb, g3, be3, m3, v3);
    k0_zero<<<(BSEG * KATT * EPAD + 255) / 256, 256>>>(w2);
    k1_gemm1<<<dim3(NPTS / 128, F0 / 128), 256>>>(x, w1);
    k2a_gemm<<<dim3(NPTS / 128, KATT / TILE_N), 256, k2a_smem>>>(0);
    k2b_pool<<<dim3(KATT / 128, NPTS / 128), 256, k2b_smem>>>(x);
    k_out2<<<2048, 256>>>(len);
    k3_fc<<<128, 256>>>(fcw);
    k4_norm<<<BSEG, 256>>>(out);
}

// round 12
// speedup vs baseline: 1.2862x; 1.2862x over previous
#include <cuda_runtime.h>
#include <cuda_bf16.h>
#include <math.h>

#define NPTS 32768
#define CIN  32
#define F0   256
#define KATT 1024
#define BSEG 16
#define KC   32768
#define EPAD 40
#define BN_EPS 1e-5f

#define TILE_N 128
#define SETU 68            /* uint stride of sEt row (128 pts bf16 + pad)   */
#define SETB 136           /* bf16 stride of sEt row                        */
#define SXTU 68            /* uint stride of sXt row                        */
#define STAGE_U (128 * 36 * 2)   /* uints per stage: A[128][36]+B[128][36] */
#define SMEM_U  (2 * STAGE_U)    /* 18432 uints = 73728 B                  */

// ---------------- scratch ----------------
__device__ unsigned g_att1b[NPTS * 128];   // bf16x2-packed att1, 16.8 MB
__device__ unsigned g_w2b[KATT * 128];     // bf16x2-packed w2, 512 KB
__device__ unsigned g_xtb[40 * (NPTS / 2)]; // x_aug transposed bf16x2 [n][pt-pair], 2.6 MB
__device__ float g_E[BSEG * KATT * EPAD];
__device__ float g_out2[BSEG * KC];
__device__ float g_rtmp[BSEG * F0];
__device__ float g_s1[F0], g_t1[F0];
__device__ float g_s2[KATT], g_t2[KATT];
__device__ float g_s3[F0], g_t3[F0];
__device__ int   g_off[BSEG + 1];

// ---------------- helpers ----------------
static __device__ __forceinline__ unsigned utf32(float x) {
    unsigned r;
    asm("cvt.rna.tf32.f32 %0, %1;" : "=r"(r) : "f"(x));
    return r;
}

static __device__ __forceinline__ unsigned packbf(float lo, float hi) {
    unsigned r;
    asm("cvt.rn.bf16x2.f32 %0, %1, %2;" : "=r"(r) : "f"(hi), "f"(lo));
    return r;
}

static __device__ __forceinline__ void mma_tf32(float* d, const unsigned* a, const unsigned* b) {
    asm volatile(
        "mma.sync.aligned.m16n8k8.row.col.f32.tf32.tf32.f32 "
        "{%0,%1,%2,%3}, {%4,%5,%6,%7}, {%8,%9}, {%0,%1,%2,%3};\n"
        : "+f"(d[0]), "+f"(d[1]), "+f"(d[2]), "+f"(d[3])
        : "r"(a[0]), "r"(a[1]), "r"(a[2]), "r"(a[3]), "r"(b[0]), "r"(b[1]));
}

static __device__ __forceinline__ void mma_bf16(float* d, const unsigned* a, const unsigned* b) {
    asm volatile(
        "mma.sync.aligned.m16n8k16.row.col.f32.bf16.bf16.f32 "
        "{%0,%1,%2,%3}, {%4,%5,%6,%7}, {%8,%9}, {%0,%1,%2,%3};\n"
        : "+f"(d[0]), "+f"(d[1]), "+f"(d[2]), "+f"(d[3])
        : "r"(a[0]), "r"(a[1]), "r"(a[2]), "r"(a[3]), "r"(b[0]), "r"(b[1]));
}

static __device__ __forceinline__ void ldsm4(unsigned& r0, unsigned& r1, unsigned& r2,
                                             unsigned& r3, unsigned a) {
    asm volatile("ldmatrix.sync.aligned.m8n8.x4.shared.b16 {%0,%1,%2,%3}, [%4];"
                 : "=r"(r0), "=r"(r1), "=r"(r2), "=r"(r3) : "r"(a));
}

static __device__ __forceinline__ void cpa16(void* s, const void* g) {
    unsigned sa = (unsigned)__cvta_generic_to_shared(s);
    asm volatile("cp.async.cg.shared.global [%0], [%1], 16;\n" :: "r"(sa), "l"(g));
}
#define CPA_COMMIT() asm volatile("cp.async.commit_group;\n" ::: "memory")
#define CPA_WAIT0()  asm volatile("cp.async.wait_group 0;\n" ::: "memory")

static __device__ __forceinline__ int seg_of(int row) {
    int s = 0;
    while (s < BSEG - 1 && row >= g_off[s + 1]) s++;
    return s;
}

// ---------------- k0_prep ----------------
__global__ void k0_prep(const int* __restrict__ len,
                        const float* __restrict__ b1, const float* __restrict__ g1,
                        const float* __restrict__ be1, const float* __restrict__ m1,
                        const float* __restrict__ v1,
                        const float* __restrict__ b2, const float* __restrict__ g2,
                        const float* __restrict__ be2, const float* __restrict__ m2,
                        const float* __restrict__ v2,
                        const float* __restrict__ fcb, const float* __restrict__ g3,
                        const float* __restrict__ be3, const float* __restrict__ m3,
                        const float* __restrict__ v3) {
    int t = threadIdx.x;
    if (t == 0) {
        int acc = 0;
        for (int i = 0; i < BSEG; i++) { g_off[i] = acc; acc += len[i]; }
        g_off[BSEG] = acc;
    }
    if (t < F0) {
        float a = g1[t] * rsqrtf(v1[t] + BN_EPS);
        g_s1[t] = a;
        g_t1[t] = (b1[t] - m1[t]) * a + be1[t];
        float a3 = g3[t] * rsqrtf(v3[t] + BN_EPS);
        g_s3[t] = a3;
        g_t3[t] = (fcb[t] - m3[t]) * a3 + be3[t];
    }
    {
        float a2 = g2[t] * rsqrtf(v2[t] + BN_EPS);
        g_s2[t] = a2;
        g_t2[t] = (b2[t] - m2[t]) * a2 + be2[t];
    }
}

// ---------------- k0_zero: zero E/rtmp + convert w2 -> bf16 + build x_aug^T ----------------
__global__ void k0_zero(const float* __restrict__ w2, const float* __restrict__ x) {
    int idx = blockIdx.x * 256 + threadIdx.x;   // grid covers 655360
    if (idx < BSEG * KATT * EPAD) g_E[idx] = 0.f;
    if (idx < BSEG * F0) g_rtmp[idx] = 0.f;
    if (idx < KATT * 128) {
        int n = idx >> 7, p = idx & 127;
        g_w2b[idx] = packbf(w2[n * F0 + 2 * p], w2[n * F0 + 2 * p + 1]);
    }
    {   // x_aug transposed: 40 * 16384 = 655360 entries (whole grid)
        int n = idx >> 14, pp = idx & 16383;
        float lo, hi;
        if (n < 32) {
            lo = x[(long)(2 * pp) * CIN + n];
            hi = x[(long)(2 * pp + 1) * CIN + n];
        } else if (n == 32) { lo = hi = 1.f; }
        else { lo = hi = 0.f; }
        g_xtb[idx] = packbf(lo, hi);
    }
}

// ---------------- k1: att1 = relu(bn1(x @ w1^T)) -> bf16 ----------------
__global__ __launch_bounds__(256) void k1_gemm1(const float* __restrict__ x,
                                                const float* __restrict__ w1) {
    __shared__ unsigned sA[128 * 36];
    __shared__ unsigned sB[128 * 36];
    int tid = threadIdx.x;
    int rowBase = blockIdx.x * 128;
    int colBase = blockIdx.y * 128;

#pragma unroll
    for (int i = 0; i < 16; i++) {
        int idx = tid + i * 256;
        int r = idx >> 5, c = idx & 31;
        sA[r * 36 + c] = utf32(x[(rowBase + r) * CIN + c]);
        sB[r * 36 + c] = utf32(w1[(colBase + r) * CIN + c]);
    }
    __syncthreads();

    int wid = tid >> 5, lane = tid & 31;
    int g = lane >> 2, tg = lane & 3;
    int wr = (wid & 1) * 64;
    int wc = (wid >> 1) * 32;
    float acc[4][4][4] = {};

#pragma unroll
    for (int ks = 0; ks < 32; ks += 8) {
        unsigned af[4][4], bf[4][2];
#pragma unroll
        for (int mt = 0; mt < 4; mt++) {
            int r0 = wr + mt * 16 + g;
            af[mt][0] = sA[r0 * 36 + ks + tg];
            af[mt][1] = sA[(r0 + 8) * 36 + ks + tg];
            af[mt][2] = sA[r0 * 36 + ks + tg + 4];
            af[mt][3] = sA[(r0 + 8) * 36 + ks + tg + 4];
        }
#pragma unroll
        for (int nt = 0; nt < 4; nt++) {
            int n0 = wc + nt * 8 + g;
            bf[nt][0] = sB[n0 * 36 + ks + tg];
            bf[nt][1] = sB[n0 * 36 + ks + tg + 4];
        }
#pragma unroll
        for (int mt = 0; mt < 4; mt++)
#pragma unroll
            for (int nt = 0; nt < 4; nt++) mma_tf32(acc[mt][nt], af[mt], bf[nt]);
    }

#pragma unroll
    for (int mt = 0; mt < 4; mt++) {
#pragma unroll
        for (int nt = 0; nt < 4; nt++) {
            int col = colBase + wc + nt * 8 + 2 * tg;
            float s0 = g_s1[col], t0 = g_t1[col];
            float s1v = g_s1[col + 1], t1v = g_t1[col + 1];
            int r0 = rowBase + wr + mt * 16 + g;
            float v0 = fmaxf(acc[mt][nt][0] * s0 + t0, 0.f);
            float v1 = fmaxf(acc[mt][nt][1] * s1v + t1v, 0.f);
            float v2 = fmaxf(acc[mt][nt][2] * s0 + t0, 0.f);
            float v3 = fmaxf(acc[mt][nt][3] * s1v + t1v, 0.f);
            g_att1b[r0 * 128 + (col >> 1)] = packbf(v0, v1);
            g_att1b[(r0 + 8) * 128 + (col >> 1)] = packbf(v2, v3);
        }
    }
}

// ---------------- k2: fused bf16 GEMM2 + exp + e^T@x_aug (x_aug via cp.async) ----------------
__global__ __launch_bounds__(256, 2) void k2_main(int dummy) {
    extern __shared__ unsigned sm[];
    unsigned* sEtU = sm;                 // [128 attcols][68] transposed bf16 e, aliased
    unsigned* sXtU = sm + 128 * SETU;    // [40][68]

    int tid = threadIdx.x;
    int rowBase = blockIdx.x * 128;
    int colBase = blockIdx.y * TILE_N;
    int wid = tid >> 5, lane = tid & 31;
    int g = lane >> 2, tg = lane & 3;
    int wr = (wid & 1) * 64;
    int wc = (wid >> 1) * 32;
    float acc[4][4][4] = {};

    const unsigned* gA = g_att1b + (long)rowBase * 128;
    const unsigned* gB = g_w2b + (long)colBase * 128;
    unsigned smBase = (unsigned)__cvta_generic_to_shared(sm);

    int aRowL = (lane & 7) + ((lane >> 3) & 1) * 8;
    int aKoff = (lane >> 4) << 2;
    int bRowL = (lane & 7) + ((lane >> 4) << 3);
    int bKoff = ((lane >> 3) & 1) << 2;

    // prologue: stage chunk 0
    {
        unsigned* sA = sm;
        unsigned* sB = sm + 128 * 36;
#pragma unroll
        for (int i = 0; i < 4; i++) {
            int u = tid + i * 256;
            int r = u >> 3, cu = u & 7;
            cpa16(sA + r * 36 + cu * 4, gA + (long)r * 128 + cu * 4);
        }
#pragma unroll
        for (int i = 0; i < 4; i++) {
            int u = tid + i * 256;
            int r = u >> 3, cu = u & 7;
            cpa16(sB + r * 36 + cu * 4, gB + (long)r * 128 + cu * 4);
        }
        CPA_COMMIT();
    }

    for (int c = 0; c < 4; c++) {
        CPA_WAIT0();
        __syncthreads();

        if (c + 1 < 4) {
            unsigned* sA = sm + ((c + 1) & 1) * STAGE_U;
            unsigned* sB = sA + 128 * 36;
            int ku = (c + 1) * 32;
#pragma unroll
            for (int i = 0; i < 4; i++) {
                int u = tid + i * 256;
                int r = u >> 3, cu = u & 7;
                cpa16(sA + r * 36 + cu * 4, gA + (long)r * 128 + ku + cu * 4);
            }
#pragma unroll
            for (int i = 0; i < 4; i++) {
                int u = tid + i * 256;
                int r = u >> 3, cu = u & 7;
                cpa16(sB + r * 36 + cu * 4, gB + (long)r * 128 + ku + cu * 4);
            }
            CPA_COMMIT();
        }

        unsigned sAb = smBase + ((c & 1) * STAGE_U) * 4;
        unsigned sBb = sAb + 128 * 36 * 4;

        unsigned aAddr[4], bAddr[2];
#pragma unroll
        for (int mt = 0; mt < 4; mt++)
            aAddr[mt] = sAb + ((wr + mt * 16 + aRowL) * 36 + aKoff) * 4;
#pragma unroll
        for (int p = 0; p < 2; p++)
            bAddr[p] = sBb + ((wc + p * 16 + bRowL) * 36 + bKoff) * 4;

#pragma unroll
        for (int j = 0; j < 4; j++) {
            unsigned af[4][4], bf[4][2];
#pragma unroll
            for (int mt = 0; mt < 4; mt++)
                ldsm4(af[mt][0], af[mt][1], af[mt][2], af[mt][3], aAddr[mt] + j * 32);
#pragma unroll
            for (int p = 0; p < 2; p++)
                ldsm4(bf[2 * p][0], bf[2 * p][1], bf[2 * p + 1][0], bf[2 * p + 1][1],
                      bAddr[p] + j * 32);
#pragma unroll
            for (int mt = 0; mt < 4; mt++)
#pragma unroll
                for (int nt = 0; nt < 4; nt++) mma_bf16(acc[mt][nt], af[mt], bf[nt]);
        }
    }

    __syncthreads();   // all mma smem reads done before aliasing

    // issue x_aug cp.async (coalesced from g_xtb): 40 rows x 16 units of 16B = 640 units
#pragma unroll
    for (int i = 0; i < 3; i++) {
        int idx = tid + i * 256;
        if (idx < 640) {
            int n = idx >> 4, q = idx & 15;
            cpa16(sXtU + n * SXTU + q * 4, g_xtb + n * (NPTS / 2) + (rowBase >> 1) + q * 4);
        }
    }
    CPA_COMMIT();

    // epilogue: e = exp(relu(bn2(acc))) -> sEt (transposed, bf16)
    __nv_bfloat16* sEtB = (__nv_bfloat16*)sEtU;
#pragma unroll
    for (int mt = 0; mt < 4; mt++) {
#pragma unroll
        for (int nt = 0; nt < 4; nt++) {
            int col = wc + nt * 8 + 2 * tg;
            int colG = colBase + col;
            float s0 = g_s2[colG], t0 = g_t2[colG];
            float s1v = g_s2[colG + 1], t1v = g_t2[colG + 1];
            int r0 = wr + mt * 16 + g;
            float e0 = __expf(fmaxf(acc[mt][nt][0] * s0 + t0, 0.f));
            float e1 = __expf(fmaxf(acc[mt][nt][1] * s1v + t1v, 0.f));
            float e2 = __expf(fmaxf(acc[mt][nt][2] * s0 + t0, 0.f));
            float e3 = __expf(fmaxf(acc[mt][nt][3] * s1v + t1v, 0.f));
            sEtB[col * SETB + r0] = __float2bfloat16_rn(e0);
            sEtB[(col + 1) * SETB + r0] = __float2bfloat16_rn(e1);
            sEtB[col * SETB + r0 + 8] = __float2bfloat16_rn(e2);
            sEtB[(col + 1) * SETB + r0 + 8] = __float2bfloat16_rn(e3);
        }
    }
    CPA_WAIT0();
    __syncthreads();

    // phase-2: per-segment e^T @ x_aug (bf16 m16n8k16, 16 pts per iter)
    int s0 = seg_of(rowBase), s1 = seg_of(rowBase + 127);
    int mcol = wid * 16;
    for (int s = s0; s <= s1; s++) {
        int lo = max(g_off[s] - rowBase, 0);
        int hi = min(g_off[s + 1] - rowBase, 128);
        float ea[5][4] = {};
        for (int kk = (lo & ~15); kk < hi; kk += 16) {
            int pA = kk + 2 * tg;
            int pB = pA + 8;
            unsigned maskA = ((pA >= lo && pA < hi) ? 0x0000FFFFu : 0u) |
                             ((pA + 1 >= lo && pA + 1 < hi) ? 0xFFFF0000u : 0u);
            unsigned maskB = ((pB >= lo && pB < hi) ? 0x0000FFFFu : 0u) |
                             ((pB + 1 >= lo && pB + 1 < hi) ? 0xFFFF0000u : 0u);
            int ub = (kk >> 1) + tg;
            unsigned af[4];
            af[0] = sEtU[(mcol + g) * SETU + ub] & maskA;
            af[1] = sEtU[(mcol + g + 8) * SETU + ub] & maskA;
            af[2] = sEtU[(mcol + g) * SETU + ub + 4] & maskB;
            af[3] = sEtU[(mcol + g + 8) * SETU + ub + 4] & maskB;
#pragma unroll
            for (int nt = 0; nt < 5; nt++) {
                unsigned bf[2];
                bf[0] = sXtU[(nt * 8 + g) * SXTU + ub];
                bf[1] = sXtU[(nt * 8 + g) * SXTU + ub + 4];
                mma_bf16(ea[nt], af, bf);
            }
        }
#pragma unroll
        for (int nt = 0; nt < 5; nt++) {
            int n = nt * 8 + 2 * tg;
            int ac0 = colBase + mcol + g;
            int ac1 = ac0 + 8;
            if (n <= 32) atomicAdd(&g_E[((long)s * KATT + ac0) * EPAD + n], ea[nt][0]);
            if (n + 1 <= 32) atomicAdd(&g_E[((long)s * KATT + ac0) * EPAD + n + 1], ea[nt][1]);
            if (n <= 32) atomicAdd(&g_E[((long)s * KATT + ac1) * EPAD + n], ea[nt][2]);
            if (n + 1 <= 32) atomicAdd(&g_E[((long)s * KATT + ac1) * EPAD + n + 1], ea[nt][3]);
        }
    }
}

// ---------------- k_out2: warp per (b,k) ----------------
__global__ void k_out2(const int* __restrict__ len) {
    int bk = blockIdx.x * 8 + (threadIdx.x >> 5);
    int lane = threadIdx.x & 31;
    int b = bk >> 10, k = bk & 1023;
    const float* Eb = &g_E[(long)bk * EPAD];
    float rcp = 1.f / (Eb[32] * (float)len[b]);
    g_out2[((long)b << 15) + (k << 5) + lane] = Eb[lane] * rcp;
}

// ---------------- k3 ----------------
__global__ __launch_bounds__(256) void k3_fc(const float* __restrict__ fcw) {
    int wg = blockIdx.x * 8 + (threadIdx.x >> 5);
    int lane = threadIdx.x & 31;
    int jg = wg & 31;
    int slice = wg >> 5;
    int j0 = jg * 8;
    int base = slice * 1024;
    float acc[8][16] = {};
    for (int it = 0; it < 32; it++) {
        int kc = base + it * 32 + lane;
        float w[8];
#pragma unroll
        for (int jj = 0; jj < 8; jj++) w[jj] = fcw[(long)(j0 + jj) * KC + kc];
#pragma unroll
        for (int bb = 0; bb < 16; bb++) {
            float o = g_out2[bb * KC + kc];
#pragma unroll
            for (int jj = 0; jj < 8; jj++) acc[jj][bb] = fmaf(o, w[jj], acc[jj][bb]);
        }
    }
#pragma unroll
    for (int jj = 0; jj < 8; jj++) {
#pragma unroll
        for (int bb = 0; bb < 16; bb++) {
            float v = acc[jj][bb];
            v += __shfl_down_sync(0xffffffffu, v, 16);
            v += __shfl_down_sync(0xffffffffu, v, 8);
            v += __shfl_down_sync(0xffffffffu, v, 4);
            v += __shfl_down_sync(0xffffffffu, v, 2);
            v += __shfl_down_sync(0xffffffffu, v, 1);
            if (lane == 0) atomicAdd(&g_rtmp[bb * F0 + j0 + jj], v);
        }
    }
}

// ---------------- k4 ----------------
__global__ void k4_norm(float* __restrict__ out) {
    int b = blockIdx.x;
    int j = threadIdx.x;
    float v = g_rtmp[b * F0 + j] * g_s3[j] + g_t3[j];
    __shared__ float red[256];
    red[j] = v * v;
    __syncthreads();
    for (int o = 128; o > 0; o >>= 1) {
        if (j < o) red[j] += red[j + o];
        __syncthreads();
    }
    float nrm = fmaxf(sqrtf(red[0]), 1e-12f);
    out[b * F0 + j] = v / nrm;
}

// ---------------- launch ----------------
extern "C" void kernel_launch(void* const* d_in, const int* in_sizes, int n_in,
                              void* d_out, int out_size) {
    const float* x   = (const float*)d_in[0];
    const int*   len = (const int*)d_in[1];
    const float* w1  = (const float*)d_in[2];
    const float* b1  = (const float*)d_in[3];
    const float* g1  = (const float*)d_in[4];
    const float* be1 = (const float*)d_in[5];
    const float* m1  = (const float*)d_in[6];
    const float* v1  = (const float*)d_in[7];
    const float* w2  = (const float*)d_in[8];
    const float* b2  = (const float*)d_in[9];
    const float* g2  = (const float*)d_in[10];
    const float* be2 = (const float*)d_in[11];
    const float* m2  = (const float*)d_in[12];
    const float* v2  = (const float*)d_in[13];
    const float* fcw = (const float*)d_in[14];
    const float* fcb = (const float*)d_in[15];
    const float* g3  = (const float*)d_in[16];
    const float* be3 = (const float*)d_in[17];
    const float* m3  = (const float*)d_in[18];
    const float* v3  = (const float*)d_in[19];
    float* out = (float*)d_out;

    const int k2_smem = SMEM_U * 4;   // 73728 B -> 2 CTAs/SM
    cudaFuncSetAttribute(k2_main, cudaFuncAttributeMaxDynamicSharedMemorySize, k2_smem);

    k0_prep<<<1, 1024>>>(len, b1, g1, be1, m1, v1, b2, g2, be2, m2, v2,
                         fcb, g3, be3, m3, v3);
    k0_zero<<<2560, 256>>>(w2, x);
    k1_gemm1<<<dim3(NPTS / 128, F0 / 128), 256>>>(x, w1);
    k2_main<<<dim3(NPTS / 128, KATT / TILE_N), 256, k2_smem>>>(0);
    k_out2<<<2048, 256>>>(len);
    k3_fc<<<128, 256>>>(fcw);
    k4_norm<<<BSEG, 256>>>(out);
}

// round 14
// speedup vs baseline: 1.2918x; 1.0043x over previous
#include <cuda_runtime.h>
#include <cuda_bf16.h>
#include <math.h>

#define NPTS 32768
#define CIN  32
#define F0   256
#define KATT 1024
#define BSEG 16
#define KC   32768
#define EPAD 40
#define BN_EPS 1e-5f

#define TILE_N 128
#define SETU 68            /* uint stride of sEt row (128 pts bf16 + pad)   */
#define SETB 136           /* bf16 stride of sEt row                        */
#define SXTU 68            /* uint stride of sXt row                        */
#define SXT_OFF 0                       /* sXt at smem offset 0 (stage-0 region) */
#define SET_OFF (40 * SXTU)             /* sEt at 2720 uints                      */
#define STAGE_U (128 * 36 * 2)   /* uints per stage: A[128][36]+B[128][36] */
#define SMEM_U  (2 * STAGE_U)    /* 18432 uints = 73728 B                  */

// ---------------- scratch ----------------
__device__ unsigned g_att1b[NPTS * 128];   // bf16x2-packed att1, 16.8 MB
__device__ unsigned g_w2b[KATT * 128];     // bf16x2-packed w2, 512 KB
__device__ unsigned g_xtb[40 * (NPTS / 2)]; // x_aug transposed bf16x2 [n][pt-pair], 2.6 MB
__device__ float g_E[BSEG * KATT * EPAD];
__device__ float g_out2[BSEG * KC];
__device__ float g_rtmp[BSEG * F0];
__device__ float g_s1[F0], g_t1[F0];
__device__ float g_s2[KATT], g_t2[KATT];
__device__ float g_s3[F0], g_t3[F0];
__device__ int   g_off[BSEG + 1];

// ---------------- helpers ----------------
static __device__ __forceinline__ unsigned utf32(float x) {
    unsigned r;
    asm("cvt.rna.tf32.f32 %0, %1;" : "=r"(r) : "f"(x));
    return r;
}

static __device__ __forceinline__ unsigned packbf(float lo, float hi) {
    unsigned r;
    asm("cvt.rn.bf16x2.f32 %0, %1, %2;" : "=r"(r) : "f"(hi), "f"(lo));
    return r;
}

static __device__ __forceinline__ void mma_tf32(float* d, const unsigned* a, const unsigned* b) {
    asm volatile(
        "mma.sync.aligned.m16n8k8.row.col.f32.tf32.tf32.f32 "
        "{%0,%1,%2,%3}, {%4,%5,%6,%7}, {%8,%9}, {%0,%1,%2,%3};\n"
        : "+f"(d[0]), "+f"(d[1]), "+f"(d[2]), "+f"(d[3])
        : "r"(a[0]), "r"(a[1]), "r"(a[2]), "r"(a[3]), "r"(b[0]), "r"(b[1]));
}

static __device__ __forceinline__ void mma_bf16(float* d, const unsigned* a, const unsigned* b) {
    asm volatile(
        "mma.sync.aligned.m16n8k16.row.col.f32.bf16.bf16.f32 "
        "{%0,%1,%2,%3}, {%4,%5,%6,%7}, {%8,%9}, {%0,%1,%2,%3};\n"
        : "+f"(d[0]), "+f"(d[1]), "+f"(d[2]), "+f"(d[3])
        : "r"(a[0]), "r"(a[1]), "r"(a[2]), "r"(a[3]), "r"(b[0]), "r"(b[1]));
}

static __device__ __forceinline__ void ldsm4(unsigned& r0, unsigned& r1, unsigned& r2,
                                             unsigned& r3, unsigned a) {
    asm volatile("ldmatrix.sync.aligned.m8n8.x4.shared.b16 {%0,%1,%2,%3}, [%4];"
                 : "=r"(r0), "=r"(r1), "=r"(r2), "=r"(r3) : "r"(a));
}

static __device__ __forceinline__ void cpa16(void* s, const void* g) {
    unsigned sa = (unsigned)__cvta_generic_to_shared(s);
    asm volatile("cp.async.cg.shared.global [%0], [%1], 16;\n" :: "r"(sa), "l"(g));
}
#define CPA_COMMIT() asm volatile("cp.async.commit_group;\n" ::: "memory")
#define CPA_WAIT0()  asm volatile("cp.async.wait_group 0;\n" ::: "memory")

static __device__ __forceinline__ int seg_of(int row) {
    int s = 0;
    while (s < BSEG - 1 && row >= g_off[s + 1]) s++;
    return s;
}

// ---------------- k0_all: offsets + BN folds + zero + w2->bf16 + x_aug^T ----------------
__global__ void k0_all(const int* __restrict__ len,
                       const float* __restrict__ w2, const float* __restrict__ x,
                       const float* __restrict__ b1, const float* __restrict__ g1,
                       const float* __restrict__ be1, const float* __restrict__ m1,
                       const float* __restrict__ v1,
                       const float* __restrict__ b2, const float* __restrict__ g2,
                       const float* __restrict__ be2, const float* __restrict__ m2,
                       const float* __restrict__ v2,
                       const float* __restrict__ fcb, const float* __restrict__ g3,
                       const float* __restrict__ be3, const float* __restrict__ m3,
                       const float* __restrict__ v3) {
    int idx = blockIdx.x * 256 + threadIdx.x;   // grid covers 655360
    if (idx == 0) {
        int acc = 0;
        for (int i = 0; i < BSEG; i++) { g_off[i] = acc; acc += len[i]; }
        g_off[BSEG] = acc;
    }
    if (idx < F0) {
        float a = g1[idx] * rsqrtf(v1[idx] + BN_EPS);
        g_s1[idx] = a;
        g_t1[idx] = (b1[idx] - m1[idx]) * a + be1[idx];
        float a3 = g3[idx] * rsqrtf(v3[idx] + BN_EPS);
        g_s3[idx] = a3;
        g_t3[idx] = (fcb[idx] - m3[idx]) * a3 + be3[idx];
    }
    if (idx < KATT) {
        float a2 = g2[idx] * rsqrtf(v2[idx] + BN_EPS);
        g_s2[idx] = a2;
        g_t2[idx] = (b2[idx] - m2[idx]) * a2 + be2[idx];
    }
    if (idx < BSEG * KATT * EPAD) g_E[idx] = 0.f;
    if (idx < BSEG * F0) g_rtmp[idx] = 0.f;
    if (idx < KATT * 128) {
        int n = idx >> 7, p = idx & 127;
        g_w2b[idx] = packbf(w2[n * F0 + 2 * p], w2[n * F0 + 2 * p + 1]);
    }
    {   // x_aug transposed: 40 * 16384 = 655360 entries (whole grid)
        int n = idx >> 14, pp = idx & 16383;
        float lo, hi;
        if (n < 32) {
            lo = x[(long)(2 * pp) * CIN + n];
            hi = x[(long)(2 * pp + 1) * CIN + n];
        } else if (n == 32) { lo = hi = 1.f; }
        else { lo = hi = 0.f; }
        g_xtb[idx] = packbf(lo, hi);
    }
}

// ---------------- k1: att1 = relu(bn1(x @ w1^T)) -> bf16 ----------------
__global__ __launch_bounds__(256) void k1_gemm1(const float* __restrict__ x,
                                                const float* __restrict__ w1) {
    __shared__ unsigned sA[128 * 36];
    __shared__ unsigned sB[128 * 36];
    int tid = threadIdx.x;
    int rowBase = blockIdx.x * 128;
    int colBase = blockIdx.y * 128;

#pragma unroll
    for (int i = 0; i < 16; i++) {
        int idx = tid + i * 256;
        int r = idx >> 5, c = idx & 31;
        sA[r * 36 + c] = utf32(x[(rowBase + r) * CIN + c]);
        sB[r * 36 + c] = utf32(w1[(colBase + r) * CIN + c]);
    }
    __syncthreads();

    int wid = tid >> 5, lane = tid & 31;
    int g = lane >> 2, tg = lane & 3;
    int wr = (wid & 1) * 64;
    int wc = (wid >> 1) * 32;
    float acc[4][4][4] = {};

#pragma unroll
    for (int ks = 0; ks < 32; ks += 8) {
        unsigned af[4][4], bf[4][2];
#pragma unroll
        for (int mt = 0; mt < 4; mt++) {
            int r0 = wr + mt * 16 + g;
            af[mt][0] = sA[r0 * 36 + ks + tg];
            af[mt][1] = sA[(r0 + 8) * 36 + ks + tg];
            af[mt][2] = sA[r0 * 36 + ks + tg + 4];
            af[mt][3] = sA[(r0 + 8) * 36 + ks + tg + 4];
        }
#pragma unroll
        for (int nt = 0; nt < 4; nt++) {
            int n0 = wc + nt * 8 + g;
            bf[nt][0] = sB[n0 * 36 + ks + tg];
            bf[nt][1] = sB[n0 * 36 + ks + tg + 4];
        }
#pragma unroll
        for (int mt = 0; mt < 4; mt++)
#pragma unroll
            for (int nt = 0; nt < 4; nt++) mma_tf32(acc[mt][nt], af[mt], bf[nt]);
    }

#pragma unroll
    for (int mt = 0; mt < 4; mt++) {
#pragma unroll
        for (int nt = 0; nt < 4; nt++) {
            int col = colBase + wc + nt * 8 + 2 * tg;
            float s0 = g_s1[col], t0 = g_t1[col];
            float s1v = g_s1[col + 1], t1v = g_t1[col + 1];
            int r0 = rowBase + wr + mt * 16 + g;
            float v0 = fmaxf(acc[mt][nt][0] * s0 + t0, 0.f);
            float v1 = fmaxf(acc[mt][nt][1] * s1v + t1v, 0.f);
            float v2 = fmaxf(acc[mt][nt][2] * s0 + t0, 0.f);
            float v3 = fmaxf(acc[mt][nt][3] * s1v + t1v, 0.f);
            g_att1b[r0 * 128 + (col >> 1)] = packbf(v0, v1);
            g_att1b[(r0 + 8) * 128 + (col >> 1)] = packbf(v2, v3);
        }
    }
}

// ---------------- k2: fused bf16 GEMM2 + exp + e^T@x_aug ----------------
// sXt at smem offset 0 (stage-0 region, free during last chunk) so its cp.async
// overlaps the final chunk's compute; sEt at +2720.
__global__ __launch_bounds__(256, 2) void k2_main(int dummy) {
    extern __shared__ unsigned sm[];
    unsigned* sXtU = sm + SXT_OFF;       // [40][68]
    unsigned* sEtU = sm + SET_OFF;       // [128 attcols][68] transposed bf16 e

    int tid = threadIdx.x;
    int rowBase = blockIdx.x * 128;
    int colBase = blockIdx.y * TILE_N;
    int wid = tid >> 5, lane = tid & 31;
    int g = lane >> 2, tg = lane & 3;
    int wr = (wid & 1) * 64;
    int wc = (wid >> 1) * 32;
    float acc[4][4][4] = {};

    const unsigned* gA = g_att1b + (long)rowBase * 128;
    const unsigned* gB = g_w2b + (long)colBase * 128;
    unsigned smBase = (unsigned)__cvta_generic_to_shared(sm);

    int aRowL = (lane & 7) + ((lane >> 3) & 1) * 8;
    int aKoff = (lane >> 4) << 2;
    int bRowL = (lane & 7) + ((lane >> 4) << 3);
    int bKoff = ((lane >> 3) & 1) << 2;

    // prologue: stage chunk 0
    {
        unsigned* sA = sm;
        unsigned* sB = sm + 128 * 36;
#pragma unroll
        for (int i = 0; i < 4; i++) {
            int u = tid + i * 256;
            int r = u >> 3, cu = u & 7;
            cpa16(sA + r * 36 + cu * 4, gA + (long)r * 128 + cu * 4);
        }
#pragma unroll
        for (int i = 0; i < 4; i++) {
            int u = tid + i * 256;
            int r = u >> 3, cu = u & 7;
            cpa16(sB + r * 36 + cu * 4, gB + (long)r * 128 + cu * 4);
        }
        CPA_COMMIT();
    }

    for (int c = 0; c < 4; c++) {
        CPA_WAIT0();
        __syncthreads();

        if (c + 1 < 4) {
            unsigned* sA = sm + ((c + 1) & 1) * STAGE_U;
            unsigned* sB = sA + 128 * 36;
            int ku = (c + 1) * 32;
#pragma unroll
            for (int i = 0; i < 4; i++) {
                int u = tid + i * 256;
                int r = u >> 3, cu = u & 7;
                cpa16(sA + r * 36 + cu * 4, gA + (long)r * 128 + ku + cu * 4);
            }
#pragma unroll
            for (int i = 0; i < 4; i++) {
                int u = tid + i * 256;
                int r = u >> 3, cu = u & 7;
                cpa16(sB + r * 36 + cu * 4, gB + (long)r * 128 + ku + cu * 4);
            }
            CPA_COMMIT();
        } else {
            // last chunk computes from stage 1; stage 0 (incl. sXt region) is dead.
            // Issue x_aug staging now so it overlaps the final chunk's MMAs.
#pragma unroll
            for (int i = 0; i < 3; i++) {
                int idx = tid + i * 256;
                if (idx < 640) {
                    int n = idx >> 4, q = idx & 15;
                    cpa16(sXtU + n * SXTU + q * 4,
                          g_xtb + n * (NPTS / 2) + (rowBase >> 1) + q * 4);
                }
            }
            CPA_COMMIT();
        }

        unsigned sAb = smBase + ((c & 1) * STAGE_U) * 4;
        unsigned sBb = sAb + 128 * 36 * 4;

        unsigned aAddr[4], bAddr[2];
#pragma unroll
        for (int mt = 0; mt < 4; mt++)
            aAddr[mt] = sAb + ((wr + mt * 16 + aRowL) * 36 + aKoff) * 4;
#pragma unroll
        for (int p = 0; p < 2; p++)
            bAddr[p] = sBb + ((wc + p * 16 + bRowL) * 36 + bKoff) * 4;

#pragma unroll
        for (int j = 0; j < 4; j++) {
            unsigned af[4][4], bf[4][2];
#pragma unroll
            for (int mt = 0; mt < 4; mt++)
                ldsm4(af[mt][0], af[mt][1], af[mt][2], af[mt][3], aAddr[mt] + j * 32);
#pragma unroll
            for (int p = 0; p < 2; p++)
                ldsm4(bf[2 * p][0], bf[2 * p][1], bf[2 * p + 1][0], bf[2 * p + 1][1],
                      bAddr[p] + j * 32);
#pragma unroll
            for (int mt = 0; mt < 4; mt++)
#pragma unroll
                for (int nt = 0; nt < 4; nt++) mma_bf16(acc[mt][nt], af[mt], bf[nt]);
        }
    }

    __syncthreads();   // all mma smem reads done before aliasing

    // epilogue: e = exp(relu(bn2(acc))) -> sEt (transposed, bf16)
    __nv_bfloat16* sEtB = (__nv_bfloat16*)sEtU;
#pragma unroll
    for (int mt = 0; mt < 4; mt++) {
#pragma unroll
        for (int nt = 0; nt < 4; nt++) {
            int col = wc + nt * 8 + 2 * tg;
            int colG = colBase + col;
            float s0 = g_s2[colG], t0 = g_t2[colG];
            float s1v = g_s2[colG + 1], t1v = g_t2[colG + 1];
            int r0 = wr + mt * 16 + g;
            float e0 = __expf(fmaxf(acc[mt][nt][0] * s0 + t0, 0.f));
            float e1 = __expf(fmaxf(acc[mt][nt][1] * s1v + t1v, 0.f));
            float e2 = __expf(fmaxf(acc[mt][nt][2] * s0 + t0, 0.f));
            float e3 = __expf(fmaxf(acc[mt][nt][3] * s1v + t1v, 0.f));
            sEtB[col * SETB + r0] = __float2bfloat16_rn(e0);
            sEtB[(col + 1) * SETB + r0] = __float2bfloat16_rn(e1);
            sEtB[col * SETB + r0 + 8] = __float2bfloat16_rn(e2);
            sEtB[(col + 1) * SETB + r0 + 8] = __float2bfloat16_rn(e3);
        }
    }
    CPA_WAIT0();
    __syncthreads();

    // phase-2: per-segment e^T @ x_aug (bf16 m16n8k16, 16 pts per iter)
    int s0 = seg_of(rowBase), s1 = seg_of(rowBase + 127);
    int mcol = wid * 16;
    for (int s = s0; s <= s1; s++) {
        int lo = max(g_off[s] - rowBase, 0);
        int hi = min(g_off[s + 1] - rowBase, 128);
        float ea[5][4] = {};
        for (int kk = (lo & ~15); kk < hi; kk += 16) {
            int pA = kk + 2 * tg;
            int pB = pA + 8;
            unsigned maskA = ((pA >= lo && pA < hi) ? 0x0000FFFFu : 0u) |
                             ((pA + 1 >= lo && pA + 1 < hi) ? 0xFFFF0000u : 0u);
            unsigned maskB = ((pB >= lo && pB < hi) ? 0x0000FFFFu : 0u) |
                             ((pB + 1 >= lo && pB + 1 < hi) ? 0xFFFF0000u : 0u);
            int ub = (kk >> 1) + tg;
            unsigned af[4];
            af[0] = sEtU[(mcol + g) * SETU + ub] & maskA;
            af[1] = sEtU[(mcol + g + 8) * SETU + ub] & maskA;
            af[2] = sEtU[(mcol + g) * SETU + ub + 4] & maskB;
            af[3] = sEtU[(mcol + g + 8) * SETU + ub + 4] & maskB;
#pragma unroll
            for (int nt = 0; nt < 5; nt++) {
                unsigned bf[2];
                bf[0] = sXtU[(nt * 8 + g) * SXTU + ub];
                bf[1] = sXtU[(nt * 8 + g) * SXTU + ub + 4];
                mma_bf16(ea[nt], af, bf);
            }
        }
#pragma unroll
        for (int nt = 0; nt < 5; nt++) {
            int n = nt * 8 + 2 * tg;
            int ac0 = colBase + mcol + g;
            int ac1 = ac0 + 8;
            if (n <= 32) atomicAdd(&g_E[((long)s * KATT + ac0) * EPAD + n], ea[nt][0]);
            if (n + 1 <= 32) atomicAdd(&g_E[((long)s * KATT + ac0) * EPAD + n + 1], ea[nt][1]);
            if (n <= 32) atomicAdd(&g_E[((long)s * KATT + ac1) * EPAD + n], ea[nt][2]);
            if (n + 1 <= 32) atomicAdd(&g_E[((long)s * KATT + ac1) * EPAD + n + 1], ea[nt][3]);
        }
    }
}

// ---------------- k_out2: warp per (b,k) ----------------
__global__ void k_out2(const int* __restrict__ len) {
    int bk = blockIdx.x * 8 + (threadIdx.x >> 5);
    int lane = threadIdx.x & 31;
    int b = bk >> 10, k = bk & 1023;
    const float* Eb = &g_E[(long)bk * EPAD];
    float rcp = 1.f / (Eb[32] * (float)len[b]);
    g_out2[((long)b << 15) + (k << 5) + lane] = Eb[lane] * rcp;
}

// ---------------- k3 ----------------
__global__ __launch_bounds__(256) void k3_fc(const float* __restrict__ fcw) {
    int wg = blockIdx.x * 8 + (threadIdx.x >> 5);
    int lane = threadIdx.x & 31;
    int jg = wg & 31;
    int slice = wg >> 5;
    int j0 = jg * 8;
    int base = slice * 1024;
    float acc[8][16] = {};
    for (int it = 0; it < 32; it++) {
        int kc = base + it * 32 + lane;
        float w[8];
#pragma unroll
        for (int jj = 0; jj < 8; jj++) w[jj] = fcw[(long)(j0 + jj) * KC + kc];
#pragma unroll
        for (int bb = 0; bb < 16; bb++) {
            float o = g_out2[bb * KC + kc];
#pragma unroll
            for (int jj = 0; jj < 8; jj++) acc[jj][bb] = fmaf(o, w[jj], acc[jj][bb]);
        }
    }
#pragma unroll
    for (int jj = 0; jj < 8; jj++) {
#pragma unroll
        for (int bb = 0; bb < 16; bb++) {
            float v = acc[jj][bb];
            v += __shfl_down_sync(0xffffffffu, v, 16);
            v += __shfl_down_sync(0xffffffffu, v, 8);
            v += __shfl_down_sync(0xffffffffu, v, 4);
            v += __shfl_down_sync(0xffffffffu, v, 2);
            v += __shfl_down_sync(0xffffffffu, v, 1);
            if (lane == 0) atomicAdd(&g_rtmp[bb * F0 + j0 + jj], v);
        }
    }
}

// ---------------- k4 ----------------
__global__ void k4_norm(float* __restrict__ out) {
    int b = blockIdx.x;
    int j = threadIdx.x;
    float v = g_rtmp[b * F0 + j] * g_s3[j] + g_t3[j];
    __shared__ float red[256];
    red[j] = v * v;
    __syncthreads();
    for (int o = 128; o > 0; o >>= 1) {
        if (j < o) red[j] += red[j + o];
        __syncthreads();
    }
    float nrm = fmaxf(sqrtf(red[0]), 1e-12f);
    out[b * F0 + j] = v / nrm;
}

// ---------------- launch ----------------
extern "C" void kernel_launch(void* const* d_in, const int* in_sizes, int n_in,
                              void* d_out, int out_size) {
    const float* x   = (const float*)d_in[0];
    const int*   len = (const int*)d_in[1];
    const float* w1  = (const float*)d_in[2];
    const float* b1  = (const float*)d_in[3];
    const float* g1  = (const float*)d_in[4];
    const float* be1 = (const float*)d_in[5];
    const float* m1  = (const float*)d_in[6];
    const float* v1  = (const float*)d_in[7];
    const float* w2  = (const float*)d_in[8];
    const float* b2  = (const float*)d_in[9];
    const float* g2  = (const float*)d_in[10];
    const float* be2 = (const float*)d_in[11];
    const float* m2  = (const float*)d_in[12];
    const float* v2  = (const float*)d_in[13];
    const float* fcw = (const float*)d_in[14];
    const float* fcb = (const float*)d_in[15];
    const float* g3  = (const float*)d_in[16];
    const float* be3 = (const float*)d_in[17];
    const float* m3  = (const float*)d_in[18];
    const float* v3  = (const float*)d_in[19];
    float* out = (float*)d_out;

    const int k2_smem = SMEM_U * 4;   // 73728 B -> 2 CTAs/SM
    cudaFuncSetAttribute(k2_main, cudaFuncAttributeMaxDynamicSharedMemorySize, k2_smem);

    k0_all<<<2560, 256>>>(len, w2, x, b1, g1, be1, m1, v1, b2, g2, be2, m2, v2,
                          fcb, g3, be3, m3, v3);
    k1_gemm1<<<dim3(NPTS / 128, F0 / 128), 256>>>(x, w1);
    k2_main<<<dim3(NPTS / 128, KATT / TILE_N), 256, k2_smem>>>(0);
    k_out2<<<2048, 256>>>(len);
    k3_fc<<<128, 256>>>(fcw);
    k4_norm<<<BSEG, 256>>>(out);
}

// round 16
// speedup vs baseline: 1.2921x; 1.0002x over previous
#include <cuda_runtime.h>
#include <cuda_bf16.h>
#include <math.h>

#define NPTS 32768
#define CIN  32
#define F0   256
#define KATT 1024
#define BSEG 16
#define KC   32768
#define EPAD 40
#define BN_EPS 1e-5f

#define TILE_N 128
#define SATT 132                 /* uint stride of resident att rows          */
#define SETU 68                  /* uint stride of sEt row                    */
#define SETB 136                 /* bf16 stride of sEt row                    */
#define SXTU 68
#define BSTAGE_OFF 16896         /* 128*132; B stages live here               */
#define BSTAGE_U   4608          /* 128*36 per stage                          */
#define SMEM_U (BSTAGE_OFF + 2 * BSTAGE_U)   /* 26112 uints = 104448 B        */
#define SX1 20                   /* uint stride for x/w1 GEMM1 staging (80B = 5x16B) */

// ---------------- scratch ----------------
__device__ unsigned g_w2b[KATT * 128];      // bf16x2-packed w2
__device__ unsigned g_xb[NPTS * 16];        // bf16x2-packed x [pt][16u], 2 MB
__device__ unsigned g_w1b[F0 * 16];         // bf16x2-packed w1
__device__ unsigned g_xtb[40 * (NPTS / 2)]; // x_aug transposed bf16x2 [n][pt-pair]
__device__ float g_E[BSEG * KATT * EPAD];
__device__ float g_out2[BSEG * KC];
__device__ float g_rtmp[BSEG * F0];
__device__ float g_s1[F0], g_t1[F0];
__device__ float g_s2[KATT], g_t2[KATT];
__device__ float g_s3[F0], g_t3[F0];
__device__ int   g_off[BSEG + 1];

// ---------------- helpers ----------------
static __device__ __forceinline__ unsigned packbf(float lo, float hi) {
    unsigned r;
    asm("cvt.rn.bf16x2.f32 %0, %1, %2;" : "=r"(r) : "f"(hi), "f"(lo));
    return r;
}

static __device__ __forceinline__ void mma_bf16(float* d, const unsigned* a, const unsigned* b) {
    asm volatile(
        "mma.sync.aligned.m16n8k16.row.col.f32.bf16.bf16.f32 "
        "{%0,%1,%2,%3}, {%4,%5,%6,%7}, {%8,%9}, {%0,%1,%2,%3};\n"
        : "+f"(d[0]), "+f"(d[1]), "+f"(d[2]), "+f"(d[3])
        : "r"(a[0]), "r"(a[1]), "r"(a[2]), "r"(a[3]), "r"(b[0]), "r"(b[1]));
}

static __device__ __forceinline__ void ldsm4(unsigned& r0, unsigned& r1, unsigned& r2,
                                             unsigned& r3, unsigned a) {
    asm volatile("ldmatrix.sync.aligned.m8n8.x4.shared.b16 {%0,%1,%2,%3}, [%4];"
                 : "=r"(r0), "=r"(r1), "=r"(r2), "=r"(r3) : "r"(a));
}

static __device__ __forceinline__ void cpa16(void* s, const void* g) {
    unsigned sa = (unsigned)__cvta_generic_to_shared(s);
    asm volatile("cp.async.cg.shared.global [%0], [%1], 16;\n" :: "r"(sa), "l"(g));
}
#define CPA_COMMIT() asm volatile("cp.async.commit_group;\n" ::: "memory")
#define CPA_WAIT0()  asm volatile("cp.async.wait_group 0;\n" ::: "memory")

static __device__ __forceinline__ int seg_of(int row) {
    int s = 0;
    while (s < BSEG - 1 && row >= g_off[s + 1]) s++;
    return s;
}

// ---------------- k0_all ----------------
__global__ void k0_all(const int* __restrict__ len,
                       const float* __restrict__ w2, const float* __restrict__ x,
                       const float* __restrict__ w1,
                       const float* __restrict__ b1, const float* __restrict__ g1,
                       const float* __restrict__ be1, const float* __restrict__ m1,
                       const float* __restrict__ v1,
                       const float* __restrict__ b2, const float* __restrict__ g2,
                       const float* __restrict__ be2, const float* __restrict__ m2,
                       const float* __restrict__ v2,
                       const float* __restrict__ fcb, const float* __restrict__ g3,
                       const float* __restrict__ be3, const float* __restrict__ m3,
                       const float* __restrict__ v3) {
    int idx = blockIdx.x * 256 + threadIdx.x;   // grid covers 655360
    if (idx == 0) {
        int acc = 0;
        for (int i = 0; i < BSEG; i++) { g_off[i] = acc; acc += len[i]; }
        g_off[BSEG] = acc;
    }
    if (idx < F0) {
        float a = g1[idx] * rsqrtf(v1[idx] + BN_EPS);
        g_s1[idx] = a;
        g_t1[idx] = (b1[idx] - m1[idx]) * a + be1[idx];
        float a3 = g3[idx] * rsqrtf(v3[idx] + BN_EPS);
        g_s3[idx] = a3;
        g_t3[idx] = (fcb[idx] - m3[idx]) * a3 + be3[idx];
    }
    if (idx < KATT) {
        float a2 = g2[idx] * rsqrtf(v2[idx] + BN_EPS);
        g_s2[idx] = a2;
        g_t2[idx] = (b2[idx] - m2[idx]) * a2 + be2[idx];
    }
    if (idx < BSEG * KATT * EPAD) g_E[idx] = 0.f;
    if (idx < BSEG * F0) g_rtmp[idx] = 0.f;
    if (idx < KATT * 128) {
        int n = idx >> 7, p = idx & 127;
        g_w2b[idx] = packbf(w2[n * F0 + 2 * p], w2[n * F0 + 2 * p + 1]);
    }
    if (idx < NPTS * 16) {
        int pt = idx >> 4, u = idx & 15;
        g_xb[idx] = packbf(x[(long)pt * CIN + 2 * u], x[(long)pt * CIN + 2 * u + 1]);
    }
    if (idx < F0 * 16) {
        int n = idx >> 4, u = idx & 15;
        g_w1b[idx] = packbf(w1[n * CIN + 2 * u], w1[n * CIN + 2 * u + 1]);
    }
    {   // x_aug transposed: 40 * 16384 = 655360 entries (whole grid)
        int n = idx >> 14, pp = idx & 16383;
        float lo, hi;
        if (n < 32) {
            lo = x[(long)(2 * pp) * CIN + n];
            hi = x[(long)(2 * pp + 1) * CIN + n];
        } else if (n == 32) { lo = hi = 1.f; }
        else { lo = hi = 0.f; }
        g_xtb[idx] = packbf(lo, hi);
    }
}

// ---------------- k2: fully fused  x -> att1(smem) -> att2 -> exp -> pooled E --------
// smem: sAtt[128][132] @0; B stages @16896 (2 x 4608). GEMM1 stages x/w1 in the
// B-stage region (stride 20u = 80B, 16B-aligned); sEt aliases sAtt; sXt uses the
// free B stage during the last chunk.
__global__ __launch_bounds__(256, 2) void k2_main(int dummy) {
    extern __shared__ unsigned sm[];
    unsigned* sAttU = sm;                 // [128][132]
    unsigned* sEtU  = sm;                 // epilogue alias [128][68]
    unsigned* sXtU  = sm + BSTAGE_OFF;    // [40][68] (stage-0 region, phase-2)

    int tid = threadIdx.x;
    int rowBase = blockIdx.x * 128;
    int colBase = blockIdx.y * TILE_N;
    int wid = tid >> 5, lane = tid & 31;
    int g = lane >> 2, tg = lane & 3;
    int wr = (wid & 1) * 64;
    int wc = (wid >> 1) * 32;
    float acc[4][4][4];

    unsigned smBase = (unsigned)__cvta_generic_to_shared(sm);

    int aRowL = (lane & 7) + ((lane >> 3) & 1) * 8;
    int aKoff = (lane >> 4) << 2;
    int bRowL = (lane & 7) + ((lane >> 4) << 3);
    int bKoff = ((lane >> 3) & 1) << 2;

    // ---- stage x tile [128][16u] and w1 [256][16u] (stride 20) into B-stage region ----
    {
        unsigned* sX1 = sm + BSTAGE_OFF;          // 128*20 = 2560
        unsigned* sW1 = sm + BSTAGE_OFF + 2560;   // 256*20 = 5120 (ends at 7680 < 9216)
#pragma unroll
        for (int i = 0; i < 2; i++) {
            int u = tid + i * 256;                // 512 units
            int r = u >> 2, q = u & 3;
            cpa16(sX1 + r * SX1 + q * 4, g_xb + (long)(rowBase + r) * 16 + q * 4);
        }
#pragma unroll
        for (int i = 0; i < 4; i++) {
            int u = tid + i * 256;                // 1024 units
            int r = u >> 2, q = u & 3;
            cpa16(sW1 + r * SX1 + q * 4, g_w1b + r * 16 + q * 4);
        }
        CPA_COMMIT();
        CPA_WAIT0();
        __syncthreads();
    }

    // ---- GEMM1: att = relu(bn1(x @ w1^T)) -> sAtt, 2 passes of 64x32 per warp ----
    {
        unsigned xb  = smBase + BSTAGE_OFF * 4;
        unsigned w1b = smBase + (BSTAGE_OFF + 2560) * 4;
#pragma unroll
        for (int p = 0; p < 2; p++) {
            int wcc = (wid >> 1) * 64 + p * 32;
#pragma unroll
            for (int mt = 0; mt < 4; mt++)
#pragma unroll
                for (int nt = 0; nt < 4; nt++)
#pragma unroll
                    for (int q = 0; q < 4; q++) acc[mt][nt][q] = 0.f;

            unsigned aA[4], bA[2];
#pragma unroll
            for (int mt = 0; mt < 4; mt++)
                aA[mt] = xb + ((wr + mt * 16 + aRowL) * SX1 + aKoff) * 4;
#pragma unroll
            for (int pp = 0; pp < 2; pp++)
                bA[pp] = w1b + ((wcc + pp * 16 + bRowL) * SX1 + bKoff) * 4;

#pragma unroll
            for (int j = 0; j < 2; j++) {
                unsigned af[4][4], bf[4][2];
#pragma unroll
                for (int mt = 0; mt < 4; mt++)
                    ldsm4(af[mt][0], af[mt][1], af[mt][2], af[mt][3], aA[mt] + j * 32);
#pragma unroll
                for (int pp = 0; pp < 2; pp++)
                    ldsm4(bf[2 * pp][0], bf[2 * pp][1], bf[2 * pp + 1][0], bf[2 * pp + 1][1],
                          bA[pp] + j * 32);
#pragma unroll
                for (int mt = 0; mt < 4; mt++)
#pragma unroll
                    for (int nt = 0; nt < 4; nt++) mma_bf16(acc[mt][nt], af[mt], bf[nt]);
            }

            // bn1 + relu -> packed bf16 att (sAtt region disjoint from staging)
#pragma unroll
            for (int mt = 0; mt < 4; mt++) {
#pragma unroll
                for (int nt = 0; nt < 4; nt++) {
                    int col = wcc + nt * 8 + 2 * tg;
                    float s0 = g_s1[col], t0 = g_t1[col];
                    float s1v = g_s1[col + 1], t1v = g_t1[col + 1];
                    int r0 = wr + mt * 16 + g;
                    float v0 = fmaxf(fmaf(acc[mt][nt][0], s0, t0), 0.f);
                    float v1 = fmaxf(fmaf(acc[mt][nt][1], s1v, t1v), 0.f);
                    float v2 = fmaxf(fmaf(acc[mt][nt][2], s0, t0), 0.f);
                    float v3 = fmaxf(fmaf(acc[mt][nt][3], s1v, t1v), 0.f);
                    sAttU[r0 * SATT + (col >> 1)] = packbf(v0, v1);
                    sAttU[(r0 + 8) * SATT + (col >> 1)] = packbf(v2, v3);
                }
            }
        }
    }
    __syncthreads();   // att complete; x/w1 staging region free

    // ---- GEMM2 mainloop: B(w2) double-buffered, A resident in sAtt ----
    const unsigned* gB = g_w2b + (long)colBase * 128;
#pragma unroll
    for (int mt = 0; mt < 4; mt++)
#pragma unroll
        for (int nt = 0; nt < 4; nt++)
#pragma unroll
            for (int q = 0; q < 4; q++) acc[mt][nt][q] = 0.f;

    // prologue: B chunk 0 into stage 0
    {
        unsigned* sB = sm + BSTAGE_OFF;
#pragma unroll
        for (int i = 0; i < 4; i++) {
            int u = tid + i * 256;
            int r = u >> 3, cu = u & 7;
            cpa16(sB + r * 36 + cu * 4, gB + (long)r * 128 + cu * 4);
        }
        CPA_COMMIT();
    }

    for (int c = 0; c < 4; c++) {
        CPA_WAIT0();
        __syncthreads();

        if (c + 1 < 4) {
            unsigned* sB = sm + BSTAGE_OFF + ((c + 1) & 1) * BSTAGE_U;
            int ku = (c + 1) * 32;
#pragma unroll
            for (int i = 0; i < 4; i++) {
                int u = tid + i * 256;
                int r = u >> 3, cu = u & 7;
                cpa16(sB + r * 36 + cu * 4, gB + (long)r * 128 + ku + cu * 4);
            }
            CPA_COMMIT();
        } else {
            // stage 0 free during last chunk: stage x_aug for phase-2
#pragma unroll
            for (int i = 0; i < 3; i++) {
                int idx = tid + i * 256;
                if (idx < 640) {
                    int n = idx >> 4, q = idx & 15;
                    cpa16(sXtU + n * SXTU + q * 4,
                          g_xtb + n * (NPTS / 2) + (rowBase >> 1) + q * 4);
                }
            }
            CPA_COMMIT();
        }

        unsigned sBb = smBase + (BSTAGE_OFF + (c & 1) * BSTAGE_U) * 4;
        unsigned aAddr[4], bAddr[2];
#pragma unroll
        for (int mt = 0; mt < 4; mt++)
            aAddr[mt] = smBase + ((wr + mt * 16 + aRowL) * SATT + c * 32 + aKoff) * 4;
#pragma unroll
        for (int p = 0; p < 2; p++)
            bAddr[p] = sBb + ((wc + p * 16 + bRowL) * 36 + bKoff) * 4;

#pragma unroll
        for (int j = 0; j < 4; j++) {
            unsigned af[4][4], bf[4][2];
#pragma unroll
            for (int mt = 0; mt < 4; mt++)
                ldsm4(af[mt][0], af[mt][1], af[mt][2], af[mt][3], aAddr[mt] + j * 32);
#pragma unroll
            for (int p = 0; p < 2; p++)
                ldsm4(bf[2 * p][0], bf[2 * p][1], bf[2 * p + 1][0], bf[2 * p + 1][1],
                      bAddr[p] + j * 32);
#pragma unroll
            for (int mt = 0; mt < 4; mt++)
#pragma unroll
                for (int nt = 0; nt < 4; nt++) mma_bf16(acc[mt][nt], af[mt], bf[nt]);
        }
    }

    __syncthreads();   // all sAtt reads done before aliasing with sEt

    // epilogue: e = exp(relu(bn2(acc))) -> sEt (transposed, bf16)
    __nv_bfloat16* sEtB = (__nv_bfloat16*)sEtU;
#pragma unroll
    for (int mt = 0; mt < 4; mt++) {
#pragma unroll
        for (int nt = 0; nt < 4; nt++) {
            int col = wc + nt * 8 + 2 * tg;
            int colG = colBase + col;
            float s0 = g_s2[colG], t0 = g_t2[colG];
            float s1v = g_s2[colG + 1], t1v = g_t2[colG + 1];
            int r0 = wr + mt * 16 + g;
            float e0 = __expf(fmaxf(fmaf(acc[mt][nt][0], s0, t0), 0.f));
            float e1 = __expf(fmaxf(fmaf(acc[mt][nt][1], s1v, t1v), 0.f));
            float e2 = __expf(fmaxf(fmaf(acc[mt][nt][2], s0, t0), 0.f));
            float e3 = __expf(fmaxf(fmaf(acc[mt][nt][3], s1v, t1v), 0.f));
            sEtB[col * SETB + r0] = __float2bfloat16_rn(e0);
            sEtB[(col + 1) * SETB + r0] = __float2bfloat16_rn(e1);
            sEtB[col * SETB + r0 + 8] = __float2bfloat16_rn(e2);
            sEtB[(col + 1) * SETB + r0 + 8] = __float2bfloat16_rn(e3);
        }
    }
    CPA_WAIT0();
    __syncthreads();

    // phase-2: per-segment e^T @ x_aug (bf16 m16n8k16, 16 pts per iter)
    int s0 = seg_of(rowBase), s1 = seg_of(rowBase + 127);
    int mcol = wid * 16;
    for (int s = s0; s <= s1; s++) {
        int lo = max(g_off[s] - rowBase, 0);
        int hi = min(g_off[s + 1] - rowBase, 128);
        float ea[5][4] = {};
        for (int kk = (lo & ~15); kk < hi; kk += 16) {
            int pA = kk + 2 * tg;
            int pB = pA + 8;
            unsigned maskA = ((pA >= lo && pA < hi) ? 0x0000FFFFu : 0u) |
                             ((pA + 1 >= lo && pA + 1 < hi) ? 0xFFFF0000u : 0u);
            unsigned maskB = ((pB >= lo && pB < hi) ? 0x0000FFFFu : 0u) |
                             ((pB + 1 >= lo && pB + 1 < hi) ? 0xFFFF0000u : 0u);
            int ub = (kk >> 1) + tg;
            unsigned af[4];
            af[0] = sEtU[(mcol + g) * SETU + ub] & maskA;
            af[1] = sEtU[(mcol + g + 8) * SETU + ub] & maskA;
            af[2] = sEtU[(mcol + g) * SETU + ub + 4] & maskB;
            af[3] = sEtU[(mcol + g + 8) * SETU + ub + 4] & maskB;
#pragma unroll
            for (int nt = 0; nt < 5; nt++) {
                unsigned bf[2];
                bf[0] = sXtU[(nt * 8 + g) * SXTU + ub];
                bf[1] = sXtU[(nt * 8 + g) * SXTU + ub + 4];
                mma_bf16(ea[nt], af, bf);
            }
        }
#pragma unroll
        for (int nt = 0; nt < 5; nt++) {
            int n = nt * 8 + 2 * tg;
            int ac0 = colBase + mcol + g;
            int ac1 = ac0 + 8;
            if (n <= 32) atomicAdd(&g_E[((long)s * KATT + ac0) * EPAD + n], ea[nt][0]);
            if (n + 1 <= 32) atomicAdd(&g_E[((long)s * KATT + ac0) * EPAD + n + 1], ea[nt][1]);
            if (n <= 32) atomicAdd(&g_E[((long)s * KATT + ac1) * EPAD + n], ea[nt][2]);
            if (n + 1 <= 32) atomicAdd(&g_E[((long)s * KATT + ac1) * EPAD + n + 1], ea[nt][3]);
        }
    }
}

// ---------------- k_out2: warp per (b,k) ----------------
__global__ void k_out2(const int* __restrict__ len) {
    int bk = blockIdx.x * 8 + (threadIdx.x >> 5);
    int lane = threadIdx.x & 31;
    int b = bk >> 10, k = bk & 1023;
    const float* Eb = &g_E[(long)bk * EPAD];
    float rcp = 1.f / (Eb[32] * (float)len[b]);
    g_out2[((long)b << 15) + (k << 5) + lane] = Eb[lane] * rcp;
}

// ---------------- k3 ----------------
__global__ __launch_bounds__(256) void k3_fc(const float* __restrict__ fcw) {
    int wg = blockIdx.x * 8 + (threadIdx.x >> 5);
    int lane = threadIdx.x & 31;
    int jg = wg & 31;
    int slice = wg >> 5;
    int j0 = jg * 8;
    int base = slice * 1024;
    float acc[8][16] = {};
    for (int it = 0; it < 32; it++) {
        int kc = base + it * 32 + lane;
        float w[8];
#pragma unroll
        for (int jj = 0; jj < 8; jj++) w[jj] = fcw[(long)(j0 + jj) * KC + kc];
#pragma unroll
        for (int bb = 0; bb < 16; bb++) {
            float o = g_out2[bb * KC + kc];
#pragma unroll
            for (int jj = 0; jj < 8; jj++) acc[jj][bb] = fmaf(o, w[jj], acc[jj][bb]);
        }
    }
#pragma unroll
    for (int jj = 0; jj < 8; jj++) {
#pragma unroll
        for (int bb = 0; bb < 16; bb++) {
            float v = acc[jj][bb];
            v += __shfl_down_sync(0xffffffffu, v, 16);
            v += __shfl_down_sync(0xffffffffu, v, 8);
            v += __shfl_down_sync(0xffffffffu, v, 4);
            v += __shfl_down_sync(0xffffffffu, v, 2);
            v += __shfl_down_sync(0xffffffffu, v, 1);
            if (lane == 0) atomicAdd(&g_rtmp[bb * F0 + j0 + jj], v);
        }
    }
}

// ---------------- k4 ----------------
__global__ void k4_norm(float* __restrict__ out) {
    int b = blockIdx.x;
    int j = threadIdx.x;
    float v = g_rtmp[b * F0 + j] * g_s3[j] + g_t3[j];
    __shared__ float red[256];
    red[j] = v * v;
    __syncthreads();
    for (int o = 128; o > 0; o >>= 1) {
        if (j < o) red[j] += red[j + o];
        __syncthreads();
    }
    float nrm = fmaxf(sqrtf(red[0]), 1e-12f);
    out[b * F0 + j] = v / nrm;
}

// ---------------- launch ----------------
extern "C" void kernel_launch(void* const* d_in, const int* in_sizes, int n_in,
                              void* d_out, int out_size) {
    const float* x   = (const float*)d_in[0];
    const int*   len = (const int*)d_in[1];
    const float* w1  = (const float*)d_in[2];
    const float* b1  = (const float*)d_in[3];
    const float* g1  = (const float*)d_in[4];
    const float* be1 = (const float*)d_in[5];
    const float* m1  = (const float*)d_in[6];
    const float* v1  = (const float*)d_in[7];
    const float* w2  = (const float*)d_in[8];
    const float* b2  = (const float*)d_in[9];
    const float* g2  = (const float*)d_in[10];
    const float* be2 = (const float*)d_in[11];
    const float* m2  = (const float*)d_in[12];
    const float* v2  = (const float*)d_in[13];
    const float* fcw = (const float*)d_in[14];
    const float* fcb = (const float*)d_in[15];
    const float* g3  = (const float*)d_in[16];
    const float* be3 = (const float*)d_in[17];
    const float* m3  = (const float*)d_in[18];
    const float* v3  = (const float*)d_in[19];
    float* out = (float*)d_out;

    const int k2_smem = SMEM_U * 4;   // 104448 B -> 2 CTAs/SM
    cudaFuncSetAttribute(k2_main, cudaFuncAttributeMaxDynamicSharedMemorySize, k2_smem);

    k0_all<<<2560, 256>>>(len, w2, x, w1, b1, g1, be1, m1, v1, b2, g2, be2, m2, v2,
                          fcb, g3, be3, m3, v3);
    k2_main<<<dim3(NPTS / 128, KATT / TILE_N), 256, k2_smem>>>(0);
    k_out2<<<2048, 256>>>(len);
    k3_fc<<<128, 256>>>(fcw);
    k4_norm<<<BSEG, 256>>>(out);
}